// round 14
// baseline (speedup 1.0000x reference)
#include <cuda_runtime.h>
#include <cuda_fp16.h>
#include <mma.h>
#include <math.h>
using namespace nvcuda;

#define N_NODES  100000
#define N_EDGES  1600000
#define N_GRAPHS 256
#define F_IN     12
#define HID      64
#define FC_DIM   140
#define POOL_CHUNKS 8
#define NBLK     391          // ceil(N_NODES/256)

// ---------------- scratch (device globals; no allocation in kernel_launch) ----
__device__ int   d_deg[N_NODES];
__device__ int   d_cursor[N_NODES];        // running CSR write position
__device__ int   d_rowstart[N_NODES + 1];
__device__ int   d_aggr[NBLK];
__device__ int   d_incl[NBLK];
__device__ int   d_flag[NBLK];             // 0=none,1=aggregate,2=inclusive
__device__ int   d_csr[N_EDGES];
__device__ __align__(16) __half d_W2h[HID * HID];
__device__ __align__(16) __half d_g [(size_t)N_NODES * HID];  // fp16 message table
__device__ __align__(16) __half d_h1[(size_t)N_NODES * HID];  // fp16 activations
__device__ __align__(16) __half d_h2[(size_t)N_NODES * HID];
__device__ float d_pooled[N_GRAPHS * FC_DIM];
__device__ int   d_starts[N_GRAPHS + 1];
__device__ int   d_is32 = 0;   // set-once monotone flag: 1 if indices are int32

__device__ __forceinline__ float htanh(float x) {
    float r;
    asm("tanh.approx.f32 %0, %1;" : "=f"(r) : "f"(x));
    return r;
}

// ---------------- fused init + dtype probe + W2->fp16 -----------------------
__global__ void k_init(const int* __restrict__ ei32, const float* __restrict__ W2) {
    int i = blockIdx.x * blockDim.x + threadIdx.x;
    if (i < N_NODES) d_deg[i] = 1;                 // self-loop in deg
    if (i < N_GRAPHS * FC_DIM) d_pooled[i] = 0.0f;
    if (i < NBLK) d_flag[i] = 0;
    if (i < HID * HID) d_W2h[i] = __float2half(W2[i]);
    // int64 (values < 2^31, LE): every odd 32-bit word is 0. int32: random ids.
    if (i < 4096 && ei32[2 * i + 1] != 0) d_is32 = 1;
}

// count only needs dst (second half of edge_index); 2 edges per thread
__global__ void k_count(const void* __restrict__ ei) {
    int e2 = blockIdx.x * blockDim.x + threadIdx.x;
    if (e2 >= N_EDGES / 2) return;
    int d0, d1;
    if (d_is32) {
        int2 p = ((const int2*)((const int*)ei + N_EDGES))[e2];
        d0 = p.x; d1 = p.y;
    } else {
        longlong2 p = ((const longlong2*)((const long long*)ei + N_EDGES))[e2];
        d0 = (int)p.x; d1 = (int)p.y;
    }
    atomicAdd(&d_deg[d0], 1);
    atomicAdd(&d_deg[d1], 1);
}

// ---------------- single-pass scan (decoupled lookback) + folded bounds -----
__global__ void k_scan(const void* __restrict__ batch) {
    int bid = blockIdx.x;
    if (bid >= NBLK) {                               // folded segment bounds
        int g = (bid - NBLK) * 256 + threadIdx.x;
        if (g > N_GRAPHS) return;
        const int*       b32 = (const int*)batch;
        const long long* b64 = (const long long*)batch;
        int is32 = d_is32;
        int lo = 0, hi = N_NODES;
        while (lo < hi) {
            int mid = (lo + hi) >> 1;
            long long v = is32 ? (long long)b32[mid] : b64[mid];
            if (v < (long long)g) lo = mid + 1; else hi = mid;
        }
        d_starts[g] = lo;
        return;
    }
    __shared__ int sh[256];
    __shared__ int s_off;
    int tid = threadIdx.x;
    int i = bid * 256 + tid;
    int v = (i < N_NODES) ? d_deg[i] - 1 : 0;
    sh[tid] = v;
    __syncthreads();
    for (int off = 1; off < 256; off <<= 1) {
        int t = (tid >= off) ? sh[tid - off] : 0;
        __syncthreads();
        sh[tid] += t;
        __syncthreads();
    }
    int total = sh[255];
    if (tid == 0) {
        volatile int* vflag = d_flag;
        volatile int* vaggr = d_aggr;
        volatile int* vincl = d_incl;
        if (bid == 0) {
            d_incl[0] = total; __threadfence(); vflag[0] = 2;
            s_off = 0;
        } else {
            d_aggr[bid] = total; __threadfence(); vflag[bid] = 1;
            int off = 0;
            for (int j = bid - 1; j >= 0; ) {
                int f;
                do { f = vflag[j]; } while (f == 0);
                if (f == 2) { off += vincl[j]; break; }
                off += vaggr[j]; j--;
            }
            d_incl[bid] = off + total; __threadfence(); vflag[bid] = 2;
            s_off = off;
        }
    }
    __syncthreads();
    int offset = s_off;
    if (i < N_NODES) {
        int rs = sh[tid] - v + offset;
        d_rowstart[i] = rs;
        d_cursor[i]   = rs;                           // scatter cursor starts here
    }
    if (bid == NBLK - 1 && tid == 255) d_rowstart[N_NODES] = offset + total;
}

// ---------------- scatter edges into CSR (grouped by dst); 2 edges/thread ---
__global__ void k_scatter(const void* __restrict__ ei) {
    int e2 = blockIdx.x * blockDim.x + threadIdx.x;
    if (e2 >= N_EDGES / 2) return;
    int s0, s1, dd0, dd1;
    if (d_is32) {
        const int* p = (const int*)ei;
        int2 sv = ((const int2*)p)[e2];
        int2 dv = ((const int2*)(p + N_EDGES))[e2];
        s0 = sv.x; s1 = sv.y; dd0 = dv.x; dd1 = dv.y;
    } else {
        const long long* p = (const long long*)ei;
        longlong2 sv = ((const longlong2*)p)[e2];
        longlong2 dv = ((const longlong2*)(p + N_EDGES))[e2];
        s0 = (int)sv.x; s1 = (int)sv.y; dd0 = (int)dv.x; dd1 = (int)dv.y;
    }
    int p0 = atomicAdd(&d_cursor[dd0], 1);
    d_csr[p0] = s0;
    int p1 = atomicAdd(&d_cursor[dd1], 1);
    d_csr[p1] = s1;
}

// ---------------- layer-1 GEMM: g = dinv * (x @ W1)  (fp16 out) -------------
__global__ void k_gemm1(const float* __restrict__ x, const float* __restrict__ W1) {
    __shared__ float Ws[F_IN * HID];
    __shared__ float xs[4][F_IN];
    int tid = threadIdx.x;                          // 256 threads, 4 rows/block
    for (int i = tid; i < F_IN * HID; i += 256) Ws[i] = W1[i];
    int lr  = tid >> 6;
    int col = tid & 63;
    int r   = blockIdx.x * 4 + lr;                  // N divisible by 4
    if (col < F_IN) xs[lr][col] = x[(size_t)r * F_IN + col];
    __syncthreads();
    float a = 0.0f;
#pragma unroll
    for (int k = 0; k < F_IN; k++) a = fmaf(xs[lr][k], Ws[k * HID + col], a);
    float dinv = rsqrtf((float)d_deg[r]);
    d_g[(size_t)r * HID + col] = __float2half(a * dinv);
}

// ---------------- pull aggregation + fused activation (fp16 h out) ----------
// 8 threads/node, 16B (8 halves) each -> one 128B line per gathered row.
__global__ void k_agg(const float* __restrict__ bias, int which) {
    int t = blockIdx.x * blockDim.x + threadIdx.x;
    int node = t >> 3;
    if (node >= N_NODES) return;
    int lane = t & 7;
    int c0 = lane << 3;
    const uint4* gp = (const uint4*)d_g;            // 8 halves per uint4

    float a[8], b2[8];
    {
        uint4 w = gp[(size_t)node * 8 + lane];      // self loop
        float2 f0 = __half22float2(*(__half2*)&w.x);
        float2 f1 = __half22float2(*(__half2*)&w.y);
        float2 f2 = __half22float2(*(__half2*)&w.z);
        float2 f3 = __half22float2(*(__half2*)&w.w);
        a[0]=f0.x; a[1]=f0.y; a[2]=f1.x; a[3]=f1.y;
        a[4]=f2.x; a[5]=f2.y; a[6]=f3.x; a[7]=f3.y;
    }
#pragma unroll
    for (int k = 0; k < 8; k++) b2[k] = 0.0f;

    int s0 = d_rowstart[node], s1 = d_rowstart[node + 1];
    int i = s0;
    for (; i + 1 < s1; i += 2) {
        int sA = d_csr[i], sB = d_csr[i + 1];
        uint4 uA = gp[(size_t)sA * 8 + lane];
        uint4 uB = gp[(size_t)sB * 8 + lane];
        float2 x0 = __half22float2(*(__half2*)&uA.x), x1 = __half22float2(*(__half2*)&uA.y);
        float2 x2 = __half22float2(*(__half2*)&uA.z), x3 = __half22float2(*(__half2*)&uA.w);
        float2 y0 = __half22float2(*(__half2*)&uB.x), y1 = __half22float2(*(__half2*)&uB.y);
        float2 y2 = __half22float2(*(__half2*)&uB.z), y3 = __half22float2(*(__half2*)&uB.w);
        a[0]+=x0.x; a[1]+=x0.y; a[2]+=x1.x; a[3]+=x1.y;
        a[4]+=x2.x; a[5]+=x2.y; a[6]+=x3.x; a[7]+=x3.y;
        b2[0]+=y0.x; b2[1]+=y0.y; b2[2]+=y1.x; b2[3]+=y1.y;
        b2[4]+=y2.x; b2[5]+=y2.y; b2[6]+=y3.x; b2[7]+=y3.y;
    }
    if (i < s1) {
        int s = d_csr[i];
        uint4 u = gp[(size_t)s * 8 + lane];
        float2 x0 = __half22float2(*(__half2*)&u.x), x1 = __half22float2(*(__half2*)&u.y);
        float2 x2 = __half22float2(*(__half2*)&u.z), x3 = __half22float2(*(__half2*)&u.w);
        a[0]+=x0.x; a[1]+=x0.y; a[2]+=x1.x; a[3]+=x1.y;
        a[4]+=x2.x; a[5]+=x2.y; a[6]+=x3.x; a[7]+=x3.y;
    }
#pragma unroll
    for (int k = 0; k < 8; k++) a[k] += b2[k];

    float di = rsqrtf((float)d_deg[node]);
    float o[8];
#pragma unroll
    for (int k = 0; k < 8; k++) o[k] = htanh(fmaf(di, a[k], bias[c0 + k]));
    __half2 h0 = __floats2half2_rn(o[0], o[1]);
    __half2 h1 = __floats2half2_rn(o[2], o[3]);
    __half2 h2 = __floats2half2_rn(o[4], o[5]);
    __half2 h3 = __floats2half2_rn(o[6], o[7]);
    uint4 u;
    u.x = *(unsigned*)&h0; u.y = *(unsigned*)&h1;
    u.z = *(unsigned*)&h2; u.w = *(unsigned*)&h3;
    uint4* dst = (uint4*)(which ? d_h2 : d_h1);
    dst[(size_t)node * 8 + lane] = u;
}

// ---------------- layer-2 GEMM via tensor cores: g = dinv*(h1 @ W2) ---------
// 128 threads (4 warps), 64 rows/block. fp16 x fp16 -> f32 HMMA (wmma).
__global__ void k_gemm2() {
    __shared__ __align__(16) __half As[64 * 64];
    __shared__ __align__(16) __half Bs[64 * 64];
    __shared__ __align__(16) float  Cs[4][16 * 72];
    int tid = threadIdx.x;
    int row0 = blockIdx.x * 64;
    // stage W2 (fp16) and A tile (zero-padded tail)
    const uint4* wp = (const uint4*)d_W2h;
    uint4* bsp = (uint4*)Bs;
    for (int i = tid; i < 512; i += 128) bsp[i] = wp[i];
    const uint4* hp = (const uint4*)d_h1;
    uint4* asp = (uint4*)As;
    for (int i = tid; i < 512; i += 128) {
        int r = i >> 3, c = i & 7;
        int gr = row0 + r;
        uint4 u = make_uint4(0u, 0u, 0u, 0u);
        if (gr < N_NODES) u = hp[(size_t)gr * 8 + c];
        asp[i] = u;
    }
    __syncthreads();
    int warp = tid >> 5;
    wmma::fragment<wmma::accumulator, 16, 16, 16, float> c[4];
#pragma unroll
    for (int n = 0; n < 4; n++) wmma::fill_fragment(c[n], 0.0f);
#pragma unroll
    for (int k = 0; k < 4; k++) {
        wmma::fragment<wmma::matrix_a, 16, 16, 16, __half, wmma::row_major> af;
        wmma::load_matrix_sync(af, As + warp * 16 * 64 + k * 16, 64);
#pragma unroll
        for (int n = 0; n < 4; n++) {
            wmma::fragment<wmma::matrix_b, 16, 16, 16, __half, wmma::row_major> bf;
            wmma::load_matrix_sync(bf, Bs + k * 16 * 64 + n * 16, 64);
            wmma::mma_sync(c[n], af, bf, c[n]);
        }
    }
#pragma unroll
    for (int n = 0; n < 4; n++)
        wmma::store_matrix_sync(&Cs[warp][n * 16], c[n], 72, wmma::mem_row_major);
    __syncwarp();
    // epilogue: each warp writes its 16 rows (scale by dinv, pack fp16)
    int lane = tid & 31;
    for (int e = lane; e < 16 * 8; e += 32) {   // 16 rows x 8 uint4
        int r = e >> 3, c8 = e & 7;
        int gr = row0 + warp * 16 + r;
        if (gr >= N_NODES) continue;
        float di = rsqrtf((float)d_deg[gr]);
        float* crow = &Cs[warp][r * 72 + c8 * 8];
        __half2 h0 = __floats2half2_rn(crow[0] * di, crow[1] * di);
        __half2 h1 = __floats2half2_rn(crow[2] * di, crow[3] * di);
        __half2 h2 = __floats2half2_rn(crow[4] * di, crow[5] * di);
        __half2 h3 = __floats2half2_rn(crow[6] * di, crow[7] * di);
        uint4 u;
        u.x = *(unsigned*)&h0; u.y = *(unsigned*)&h1;
        u.z = *(unsigned*)&h2; u.w = *(unsigned*)&h3;
        ((uint4*)d_g)[(size_t)gr * 8 + c8] = u;
    }
}

// ---------------- pooled[g] += sum over nodes of [x | h1 | h2] --------------
__global__ void k_pool(const float* __restrict__ x) {
    int g = blockIdx.x >> 3;
    int chunk = blockIdx.x & (POOL_CHUNKS - 1);
    int s = d_starts[g], e = d_starts[g + 1];
    int len = e - s;
    int cs = s + (int)(((long long)len * chunk) / POOL_CHUNKS);
    int ce = s + (int)(((long long)len * (chunk + 1)) / POOL_CHUNKS);
    int c = threadIdx.x;                             // 140 threads
    float sum = 0.0f;
    if (c < F_IN) {
        for (int i = cs; i < ce; i++) sum += x[(size_t)i * F_IN + c];
    } else if (c < F_IN + HID) {
        int cc = c - F_IN;
        for (int i = cs; i < ce; i++) sum += __half2float(d_h1[(size_t)i * HID + cc]);
    } else {
        int cc = c - F_IN - HID;
        for (int i = cs; i < ce; i++) sum += __half2float(d_h2[(size_t)i * HID + cc]);
    }
    atomicAdd(&d_pooled[g * FC_DIM + c], sum);
}

// ---------------- final FC: out = pooled @ fc_W^T + fc_b --------------------
__global__ void k_fc(const float* __restrict__ fcW, const float* __restrict__ fcb,
                     float* __restrict__ out) {
    __shared__ float ps[FC_DIM];
    int g = blockIdx.x;
    int o = threadIdx.x;                             // 140 threads
    ps[o] = d_pooled[g * FC_DIM + o];
    __syncthreads();
    float a = fcb[o];
#pragma unroll 4
    for (int k = 0; k < FC_DIM; k++) a = fmaf(ps[k], fcW[o * FC_DIM + k], a);
    out[g * FC_DIM + o] = a;
}

// ---------------- launch ----------------------------------------------------
extern "C" void kernel_launch(void* const* d_in, const int* in_sizes, int n_in,
                              void* d_out, int out_size) {
    const float* x    = (const float*)d_in[0];
    const float* W1   = (const float*)d_in[1];
    const float* b1   = (const float*)d_in[2];
    const float* W2   = (const float*)d_in[3];
    const float* b2   = (const float*)d_in[4];
    const float* fcW  = (const float*)d_in[5];
    const float* fcb  = (const float*)d_in[6];
    const void*  ei   = d_in[7];
    const void*  batch= d_in[8];
    float*       out  = (float*)d_out;

    // preprocessing: init+probe+W2h, degrees, scan(+bounds), CSR
    k_init   <<<(N_NODES + 255) / 256, 256>>>((const int*)ei, W2);
    k_count  <<<(N_EDGES / 2 + 255) / 256, 256>>>(ei);
    k_scan   <<<NBLK + 2, 256>>>(batch);
    k_scatter<<<(N_EDGES / 2 + 255) / 256, 256>>>(ei);

    // layer 1
    k_gemm1<<<N_NODES / 4, 256>>>(x, W1);
    k_agg  <<<(N_NODES * 8 + 255) / 256, 256>>>(b1, 0);

    // layer 2
    k_gemm2<<<(N_NODES + 63) / 64, 128>>>();
    k_agg  <<<(N_NODES * 8 + 255) / 256, 256>>>(b2, 1);

    // pooling + FC
    k_pool<<<N_GRAPHS * POOL_CHUNKS, FC_DIM>>>(x);
    k_fc  <<<N_GRAPHS, FC_DIM>>>(fcW, fcb, out);
}

// round 16
// speedup vs baseline: 1.1452x; 1.1452x over previous
#include <cuda_runtime.h>
#include <cuda_fp16.h>
#include <mma.h>
#include <math.h>
using namespace nvcuda;

#define N_NODES  100000
#define N_EDGES  1600000
#define N_GRAPHS 256
#define F_IN     12
#define HID      64
#define FC_DIM   140
#define POOL_CHUNKS 8
#define NBLK     391          // ceil(N_NODES/256)

// ---------------- scratch (device globals; no allocation in kernel_launch) ----
__device__ int   d_deg[N_NODES];
__device__ int   d_cursor[N_NODES];        // running CSR write position
__device__ int   d_rowstart[N_NODES + 1];
__device__ int   d_bsum[NBLK];
__device__ int   d_csr[N_EDGES];
__device__ __align__(16) __half d_W2h[HID * HID];
__device__ __align__(16) __half d_g [(size_t)N_NODES * HID];  // fp16 message table
__device__ __align__(16) __half d_h1[(size_t)N_NODES * HID];  // fp16 activations
__device__ __align__(16) __half d_h2[(size_t)N_NODES * HID];
__device__ float d_pooled[N_GRAPHS * FC_DIM];
__device__ int   d_starts[N_GRAPHS + 1];
__device__ int   d_is32 = 0;   // set-once monotone flag: 1 if indices are int32

__device__ __forceinline__ float htanh(float x) {
    float r;
    asm("tanh.approx.f32 %0, %1;" : "=f"(r) : "f"(x));
    return r;
}

// ---------------- fused init + dtype probe + W2->fp16 -----------------------
__global__ void k_init(const int* __restrict__ ei32, const float* __restrict__ W2) {
    int i = blockIdx.x * blockDim.x + threadIdx.x;
    if (i < N_NODES) d_deg[i] = 1;                 // self-loop in deg
    if (i < N_GRAPHS * FC_DIM) d_pooled[i] = 0.0f;
    if (i < HID * HID) d_W2h[i] = __float2half(W2[i]);
    // int64 (values < 2^31, LE): every odd 32-bit word is 0. int32: random ids.
    if (i < 4096 && ei32[2 * i + 1] != 0) d_is32 = 1;
}

// count only needs dst (second half of edge_index); 2 edges per thread
__global__ void k_count(const void* __restrict__ ei) {
    int e2 = blockIdx.x * blockDim.x + threadIdx.x;
    if (e2 >= N_EDGES / 2) return;
    int d0, d1;
    if (d_is32) {
        int2 p = ((const int2*)((const int*)ei + N_EDGES))[e2];
        d0 = p.x; d1 = p.y;
    } else {
        longlong2 p = ((const longlong2*)((const long long*)ei + N_EDGES))[e2];
        d0 = (int)p.x; d1 = (int)p.y;
    }
    atomicAdd(&d_deg[d0], 1);
    atomicAdd(&d_deg[d1], 1);
}

// ---------------- scan phase 1: per-block sums (+ folded k_bounds) ----------
__global__ void k_scan_part(const void* __restrict__ batch) {
    int bid = blockIdx.x;
    if (bid >= NBLK) {                               // folded segment bounds
        int g = (bid - NBLK) * 256 + threadIdx.x;
        if (g > N_GRAPHS) return;
        const int*       b32 = (const int*)batch;
        const long long* b64 = (const long long*)batch;
        int is32 = d_is32;
        int lo = 0, hi = N_NODES;
        while (lo < hi) {
            int mid = (lo + hi) >> 1;
            long long v = is32 ? (long long)b32[mid] : b64[mid];
            if (v < (long long)g) lo = mid + 1; else hi = mid;
        }
        d_starts[g] = lo;
        return;
    }
    __shared__ int sh[8];
    int tid = threadIdx.x;
    int i = bid * 256 + tid;
    int v = (i < N_NODES) ? d_deg[i] - 1 : 0;
    for (int o = 16; o > 0; o >>= 1) v += __shfl_down_sync(0xffffffff, v, o);
    if ((tid & 31) == 0) sh[tid >> 5] = v;
    __syncthreads();
    if (tid < 8) {
        int s = sh[tid];
        for (int o = 4; o > 0; o >>= 1) s += __shfl_down_sync(0xff, s, o);
        if (tid == 0) d_bsum[bid] = s;
    }
}

// ---------------- scan phase 2: offset reduce + local scan + write ----------
__global__ void k_scan_write() {
    __shared__ int sh[256];
    __shared__ int ws[8];
    int tid = threadIdx.x, bid = blockIdx.x;
    // offset = sum of d_bsum[0..bid-1] (<=391 ints, L2-hot)
    int part = 0;
    for (int j = tid; j < bid; j += 256) part += d_bsum[j];
    for (int o = 16; o > 0; o >>= 1) part += __shfl_down_sync(0xffffffff, part, o);
    if ((tid & 31) == 0) ws[tid >> 5] = part;
    __syncthreads();
    if (tid < 8) {
        int s = ws[tid];
        for (int o = 4; o > 0; o >>= 1) s += __shfl_down_sync(0xff, s, o);
        if (tid == 0) ws[0] = s;
    }
    __syncthreads();
    int offset = ws[0];
    // local inclusive scan of deg-1
    int i = bid * 256 + tid;
    int v = (i < N_NODES) ? d_deg[i] - 1 : 0;
    sh[tid] = v;
    __syncthreads();
    for (int off = 1; off < 256; off <<= 1) {
        int t = (tid >= off) ? sh[tid - off] : 0;
        __syncthreads();
        sh[tid] += t;
        __syncthreads();
    }
    if (i < N_NODES) {
        int rs = sh[tid] - v + offset;
        d_rowstart[i] = rs;
        d_cursor[i]   = rs;                           // scatter cursor starts here
    }
    if (bid == NBLK - 1 && tid == 255) d_rowstart[N_NODES] = offset + sh[255];
}

// ---------------- scatter edges into CSR (grouped by dst); 2 edges/thread ---
__global__ void k_scatter(const void* __restrict__ ei) {
    int e2 = blockIdx.x * blockDim.x + threadIdx.x;
    if (e2 >= N_EDGES / 2) return;
    int s0, s1, dd0, dd1;
    if (d_is32) {
        const int* p = (const int*)ei;
        int2 sv = ((const int2*)p)[e2];
        int2 dv = ((const int2*)(p + N_EDGES))[e2];
        s0 = sv.x; s1 = sv.y; dd0 = dv.x; dd1 = dv.y;
    } else {
        const long long* p = (const long long*)ei;
        longlong2 sv = ((const longlong2*)p)[e2];
        longlong2 dv = ((const longlong2*)(p + N_EDGES))[e2];
        s0 = (int)sv.x; s1 = (int)sv.y; dd0 = (int)dv.x; dd1 = (int)dv.y;
    }
    int p0 = atomicAdd(&d_cursor[dd0], 1);
    d_csr[p0] = s0;
    int p1 = atomicAdd(&d_cursor[dd1], 1);
    d_csr[p1] = s1;
}

// ---------------- layer-1 GEMM: g = dinv * (x @ W1)  (fp16 out) -------------
__global__ void k_gemm1(const float* __restrict__ x, const float* __restrict__ W1) {
    __shared__ float Ws[F_IN * HID];
    __shared__ float xs[4][F_IN];
    int tid = threadIdx.x;                          // 256 threads, 4 rows/block
    for (int i = tid; i < F_IN * HID; i += 256) Ws[i] = W1[i];
    int lr  = tid >> 6;
    int col = tid & 63;
    int r   = blockIdx.x * 4 + lr;                  // N divisible by 4
    if (col < F_IN) xs[lr][col] = x[(size_t)r * F_IN + col];
    __syncthreads();
    float a = 0.0f;
#pragma unroll
    for (int k = 0; k < F_IN; k++) a = fmaf(xs[lr][k], Ws[k * HID + col], a);
    float dinv = rsqrtf((float)d_deg[r]);
    d_g[(size_t)r * HID + col] = __float2half(a * dinv);
}

// ---------------- pull aggregation + fused activation (fp16 h out) ----------
// 8 threads/node, 16B (8 halves) each -> one 128B line per gathered row.
__global__ void k_agg(const float* __restrict__ bias, int which) {
    int t = blockIdx.x * blockDim.x + threadIdx.x;
    int node = t >> 3;
    if (node >= N_NODES) return;
    int lane = t & 7;
    int c0 = lane << 3;
    const uint4* gp = (const uint4*)d_g;            // 8 halves per uint4

    float a[8], b2[8];
    {
        uint4 w = gp[(size_t)node * 8 + lane];      // self loop
        float2 f0 = __half22float2(*(__half2*)&w.x);
        float2 f1 = __half22float2(*(__half2*)&w.y);
        float2 f2 = __half22float2(*(__half2*)&w.z);
        float2 f3 = __half22float2(*(__half2*)&w.w);
        a[0]=f0.x; a[1]=f0.y; a[2]=f1.x; a[3]=f1.y;
        a[4]=f2.x; a[5]=f2.y; a[6]=f3.x; a[7]=f3.y;
    }
#pragma unroll
    for (int k = 0; k < 8; k++) b2[k] = 0.0f;

    int s0 = d_rowstart[node], s1 = d_rowstart[node + 1];
    int i = s0;
    for (; i + 1 < s1; i += 2) {
        int sA = d_csr[i], sB = d_csr[i + 1];
        uint4 uA = gp[(size_t)sA * 8 + lane];
        uint4 uB = gp[(size_t)sB * 8 + lane];
        float2 x0 = __half22float2(*(__half2*)&uA.x), x1 = __half22float2(*(__half2*)&uA.y);
        float2 x2 = __half22float2(*(__half2*)&uA.z), x3 = __half22float2(*(__half2*)&uA.w);
        float2 y0 = __half22float2(*(__half2*)&uB.x), y1 = __half22float2(*(__half2*)&uB.y);
        float2 y2 = __half22float2(*(__half2*)&uB.z), y3 = __half22float2(*(__half2*)&uB.w);
        a[0]+=x0.x; a[1]+=x0.y; a[2]+=x1.x; a[3]+=x1.y;
        a[4]+=x2.x; a[5]+=x2.y; a[6]+=x3.x; a[7]+=x3.y;
        b2[0]+=y0.x; b2[1]+=y0.y; b2[2]+=y1.x; b2[3]+=y1.y;
        b2[4]+=y2.x; b2[5]+=y2.y; b2[6]+=y3.x; b2[7]+=y3.y;
    }
    if (i < s1) {
        int s = d_csr[i];
        uint4 u = gp[(size_t)s * 8 + lane];
        float2 x0 = __half22float2(*(__half2*)&u.x), x1 = __half22float2(*(__half2*)&u.y);
        float2 x2 = __half22float2(*(__half2*)&u.z), x3 = __half22float2(*(__half2*)&u.w);
        a[0]+=x0.x; a[1]+=x0.y; a[2]+=x1.x; a[3]+=x1.y;
        a[4]+=x2.x; a[5]+=x2.y; a[6]+=x3.x; a[7]+=x3.y;
    }
#pragma unroll
    for (int k = 0; k < 8; k++) a[k] += b2[k];

    float di = rsqrtf((float)d_deg[node]);
    float o[8];
#pragma unroll
    for (int k = 0; k < 8; k++) o[k] = htanh(fmaf(di, a[k], bias[c0 + k]));
    __half2 h0 = __floats2half2_rn(o[0], o[1]);
    __half2 h1 = __floats2half2_rn(o[2], o[3]);
    __half2 h2 = __floats2half2_rn(o[4], o[5]);
    __half2 h3 = __floats2half2_rn(o[6], o[7]);
    uint4 u;
    u.x = *(unsigned*)&h0; u.y = *(unsigned*)&h1;
    u.z = *(unsigned*)&h2; u.w = *(unsigned*)&h3;
    uint4* dst = (uint4*)(which ? d_h2 : d_h1);
    dst[(size_t)node * 8 + lane] = u;
}

// ---------------- layer-2 GEMM via tensor cores: g = dinv*(h1 @ W2) ---------
// 128 threads (4 warps), 64 rows/block. fp16 x fp16 -> f32 HMMA (wmma).
__global__ void k_gemm2() {
    __shared__ __align__(16) __half As[64 * 64];
    __shared__ __align__(16) __half Bs[64 * 64];
    __shared__ __align__(16) float  Cs[4][16 * 72];
    int tid = threadIdx.x;
    int row0 = blockIdx.x * 64;
    // stage W2 (fp16) and A tile (zero-padded tail)
    const uint4* wp = (const uint4*)d_W2h;
    uint4* bsp = (uint4*)Bs;
    for (int i = tid; i < 512; i += 128) bsp[i] = wp[i];
    const uint4* hp = (const uint4*)d_h1;
    uint4* asp = (uint4*)As;
    for (int i = tid; i < 512; i += 128) {
        int r = i >> 3, c = i & 7;
        int gr = row0 + r;
        uint4 u = make_uint4(0u, 0u, 0u, 0u);
        if (gr < N_NODES) u = hp[(size_t)gr * 8 + c];
        asp[i] = u;
    }
    __syncthreads();
    int warp = tid >> 5;
    wmma::fragment<wmma::accumulator, 16, 16, 16, float> c[4];
#pragma unroll
    for (int n = 0; n < 4; n++) wmma::fill_fragment(c[n], 0.0f);
#pragma unroll
    for (int k = 0; k < 4; k++) {
        wmma::fragment<wmma::matrix_a, 16, 16, 16, __half, wmma::row_major> af;
        wmma::load_matrix_sync(af, As + warp * 16 * 64 + k * 16, 64);
#pragma unroll
        for (int n = 0; n < 4; n++) {
            wmma::fragment<wmma::matrix_b, 16, 16, 16, __half, wmma::row_major> bf;
            wmma::load_matrix_sync(bf, Bs + k * 16 * 64 + n * 16, 64);
            wmma::mma_sync(c[n], af, bf, c[n]);
        }
    }
#pragma unroll
    for (int n = 0; n < 4; n++)
        wmma::store_matrix_sync(&Cs[warp][n * 16], c[n], 72, wmma::mem_row_major);
    __syncwarp();
    // epilogue: each warp writes its 16 rows (scale by dinv, pack fp16)
    int lane = tid & 31;
    for (int e = lane; e < 16 * 8; e += 32) {   // 16 rows x 8 uint4
        int r = e >> 3, c8 = e & 7;
        int gr = row0 + warp * 16 + r;
        if (gr >= N_NODES) continue;
        float di = rsqrtf((float)d_deg[gr]);
        float* crow = &Cs[warp][r * 72 + c8 * 8];
        __half2 h0 = __floats2half2_rn(crow[0] * di, crow[1] * di);
        __half2 h1 = __floats2half2_rn(crow[2] * di, crow[3] * di);
        __half2 h2 = __floats2half2_rn(crow[4] * di, crow[5] * di);
        __half2 h3 = __floats2half2_rn(crow[6] * di, crow[7] * di);
        uint4 u;
        u.x = *(unsigned*)&h0; u.y = *(unsigned*)&h1;
        u.z = *(unsigned*)&h2; u.w = *(unsigned*)&h3;
        ((uint4*)d_g)[(size_t)gr * 8 + c8] = u;
    }
}

// ---------------- pooled[g] += sum over nodes of [x | h1 | h2] --------------
__global__ void k_pool(const float* __restrict__ x) {
    int g = blockIdx.x >> 3;
    int chunk = blockIdx.x & (POOL_CHUNKS - 1);
    int s = d_starts[g], e = d_starts[g + 1];
    int len = e - s;
    int cs = s + (int)(((long long)len * chunk) / POOL_CHUNKS);
    int ce = s + (int)(((long long)len * (chunk + 1)) / POOL_CHUNKS);
    int c = threadIdx.x;                             // 140 threads
    float sum = 0.0f;
    if (c < F_IN) {
        for (int i = cs; i < ce; i++) sum += x[(size_t)i * F_IN + c];
    } else if (c < F_IN + HID) {
        int cc = c - F_IN;
        for (int i = cs; i < ce; i++) sum += __half2float(d_h1[(size_t)i * HID + cc]);
    } else {
        int cc = c - F_IN - HID;
        for (int i = cs; i < ce; i++) sum += __half2float(d_h2[(size_t)i * HID + cc]);
    }
    atomicAdd(&d_pooled[g * FC_DIM + c], sum);
}

// ---------------- final FC: out = pooled @ fc_W^T + fc_b --------------------
__global__ void k_fc(const float* __restrict__ fcW, const float* __restrict__ fcb,
                     float* __restrict__ out) {
    __shared__ float ps[FC_DIM];
    int g = blockIdx.x;
    int o = threadIdx.x;                             // 140 threads
    ps[o] = d_pooled[g * FC_DIM + o];
    __syncthreads();
    float a = fcb[o];
#pragma unroll 4
    for (int k = 0; k < FC_DIM; k++) a = fmaf(ps[k], fcW[o * FC_DIM + k], a);
    out[g * FC_DIM + o] = a;
}

// ---------------- launch ----------------------------------------------------
extern "C" void kernel_launch(void* const* d_in, const int* in_sizes, int n_in,
                              void* d_out, int out_size) {
    const float* x    = (const float*)d_in[0];
    const float* W1   = (const float*)d_in[1];
    const float* b1   = (const float*)d_in[2];
    const float* W2   = (const float*)d_in[3];
    const float* b2   = (const float*)d_in[4];
    const float* fcW  = (const float*)d_in[5];
    const float* fcb  = (const float*)d_in[6];
    const void*  ei   = d_in[7];
    const void*  batch= d_in[8];
    float*       out  = (float*)d_out;

    // preprocessing: init+probe+W2h, degrees, scan(+bounds), CSR
    k_init      <<<(N_NODES + 255) / 256, 256>>>((const int*)ei, W2);
    k_count     <<<(N_EDGES / 2 + 255) / 256, 256>>>(ei);
    k_scan_part <<<NBLK + 2, 256>>>(batch);
    k_scan_write<<<NBLK, 256>>>();
    k_scatter   <<<(N_EDGES / 2 + 255) / 256, 256>>>(ei);

    // layer 1
    k_gemm1<<<N_NODES / 4, 256>>>(x, W1);
    k_agg  <<<(N_NODES * 8 + 255) / 256, 256>>>(b1, 0);

    // layer 2
    k_gemm2<<<(N_NODES + 63) / 64, 128>>>();
    k_agg  <<<(N_NODES * 8 + 255) / 256, 256>>>(b2, 1);

    // pooling + FC
    k_pool<<<N_GRAPHS * POOL_CHUNKS, FC_DIM>>>(x);
    k_fc  <<<N_GRAPHS, FC_DIM>>>(fcW, fcb, out);
}

// round 17
// speedup vs baseline: 1.1624x; 1.0150x over previous
#include <cuda_runtime.h>
#include <cuda_fp16.h>
#include <mma.h>
#include <math.h>
using namespace nvcuda;

#define N_NODES  100000
#define N_EDGES  1600000
#define N_GRAPHS 256
#define F_IN     12
#define HID      64
#define FC_DIM   140
#define POOL_CHUNKS 8
#define NBLK     391          // ceil(N_NODES/256)
#define SCAT_BLKS 3125        // N_EDGES/2/256
#define GEMM1_BLKS (N_NODES / 4)

// ---------------- scratch (device globals; statically zeroed) ---------------
__device__ int   d_deg[N_NODES];           // 0 at start; restored to 0 by k_pool
__device__ int   d_cursor[N_NODES];        // running CSR write position
__device__ int   d_rowstart[N_NODES + 1];
__device__ int   d_bsum[NBLK];
__device__ int   d_csr[N_EDGES];
__device__ __align__(16) __half d_W2h[HID * HID];
__device__ __align__(16) __half d_g [(size_t)N_NODES * HID];  // fp16 message table
__device__ __align__(16) __half d_h1[(size_t)N_NODES * HID];  // fp16 activations
__device__ __align__(16) __half d_h2[(size_t)N_NODES * HID];
__device__ float d_parts[N_GRAPHS * POOL_CHUNKS * FC_DIM];    // always overwritten
__device__ int   d_starts[N_GRAPHS + 1];
__device__ int   d_is32 = 0;   // set-once monotone flag: 1 if indices are int32

__device__ __forceinline__ float htanh(float x) {
    float r;
    asm("tanh.approx.f32 %0, %1;" : "=f"(r) : "f"(x));
    return r;
}

// ---------------- dtype probe ------------------------------------------------
// int64 (values < 2^31, LE): every odd 32-bit word is 0. int32: random ids.
__global__ void k_probe(const int* __restrict__ ei32) {
    int i = blockIdx.x * blockDim.x + threadIdx.x;
    if (ei32[2 * i + 1] != 0) d_is32 = 1;
}

// ---------------- degree count (deg starts at 0) + folded W2->fp16 ----------
__global__ void k_count(const void* __restrict__ ei, const float* __restrict__ W2) {
    int bid = blockIdx.x;
    if (bid >= SCAT_BLKS) {                          // folded W2 conversion
        int i = (bid - SCAT_BLKS) * 256 + threadIdx.x;
        if (i < HID * HID) d_W2h[i] = __float2half(W2[i]);
        return;
    }
    int e2 = bid * 256 + threadIdx.x;                // 2 edges per thread
    int d0, d1;
    if (d_is32) {
        int2 p = ((const int2*)((const int*)ei + N_EDGES))[e2];
        d0 = p.x; d1 = p.y;
    } else {
        longlong2 p = ((const longlong2*)((const long long*)ei + N_EDGES))[e2];
        d0 = (int)p.x; d1 = (int)p.y;
    }
    atomicAdd(&d_deg[d0], 1);
    atomicAdd(&d_deg[d1], 1);
}

// ---------------- scan phase 1: per-block sums (+ folded k_bounds) ----------
__global__ void k_scan_part(const void* __restrict__ batch) {
    int bid = blockIdx.x;
    if (bid >= NBLK) {                               // folded segment bounds
        int g = (bid - NBLK) * 256 + threadIdx.x;
        if (g > N_GRAPHS) return;
        const int*       b32 = (const int*)batch;
        const long long* b64 = (const long long*)batch;
        int is32 = d_is32;
        int lo = 0, hi = N_NODES;
        while (lo < hi) {
            int mid = (lo + hi) >> 1;
            long long v = is32 ? (long long)b32[mid] : b64[mid];
            if (v < (long long)g) lo = mid + 1; else hi = mid;
        }
        d_starts[g] = lo;
        return;
    }
    __shared__ int sh[8];
    int tid = threadIdx.x;
    int i = bid * 256 + tid;
    int v = (i < N_NODES) ? d_deg[i] : 0;
    for (int o = 16; o > 0; o >>= 1) v += __shfl_down_sync(0xffffffff, v, o);
    if ((tid & 31) == 0) sh[tid >> 5] = v;
    __syncthreads();
    if (tid < 8) {
        int s = sh[tid];
        for (int o = 4; o > 0; o >>= 1) s += __shfl_down_sync(0xff, s, o);
        if (tid == 0) d_bsum[bid] = s;
    }
}

// ---------------- scan phase 2: offset reduce + local scan + write ----------
__global__ void k_scan_write() {
    __shared__ int sh[256];
    __shared__ int ws[8];
    int tid = threadIdx.x, bid = blockIdx.x;
    int part = 0;
    for (int j = tid; j < bid; j += 256) part += d_bsum[j];
    for (int o = 16; o > 0; o >>= 1) part += __shfl_down_sync(0xffffffff, part, o);
    if ((tid & 31) == 0) ws[tid >> 5] = part;
    __syncthreads();
    if (tid < 8) {
        int s = ws[tid];
        for (int o = 4; o > 0; o >>= 1) s += __shfl_down_sync(0xff, s, o);
        if (tid == 0) ws[0] = s;
    }
    __syncthreads();
    int offset = ws[0];
    int i = bid * 256 + tid;
    int v = (i < N_NODES) ? d_deg[i] : 0;
    sh[tid] = v;
    __syncthreads();
    for (int off = 1; off < 256; off <<= 1) {
        int t = (tid >= off) ? sh[tid - off] : 0;
        __syncthreads();
        sh[tid] += t;
        __syncthreads();
    }
    if (i < N_NODES) {
        int rs = sh[tid] - v + offset;
        d_rowstart[i] = rs;
        d_cursor[i]   = rs;
    }
    if (bid == NBLK - 1 && tid == 255) d_rowstart[N_NODES] = offset + sh[255];
}

// ---------------- fused: scatter (CSR fill) + layer-1 GEMM ------------------
__global__ void k_scatter_gemm1(const void* __restrict__ ei,
                                const float* __restrict__ x,
                                const float* __restrict__ W1) {
    int bid = blockIdx.x;
    if (bid < SCAT_BLKS) {                           // ---- scatter part
        int e2 = bid * 256 + threadIdx.x;            // 2 edges per thread
        int s0, s1, dd0, dd1;
        if (d_is32) {
            const int* p = (const int*)ei;
            int2 sv = ((const int2*)p)[e2];
            int2 dv = ((const int2*)(p + N_EDGES))[e2];
            s0 = sv.x; s1 = sv.y; dd0 = dv.x; dd1 = dv.y;
        } else {
            const long long* p = (const long long*)ei;
            longlong2 sv = ((const longlong2*)p)[e2];
            longlong2 dv = ((const longlong2*)(p + N_EDGES))[e2];
            s0 = (int)sv.x; s1 = (int)sv.y; dd0 = (int)dv.x; dd1 = (int)dv.y;
        }
        int p0 = atomicAdd(&d_cursor[dd0], 1);
        d_csr[p0] = s0;
        int p1 = atomicAdd(&d_cursor[dd1], 1);
        d_csr[p1] = s1;
        return;
    }
    // ---- gemm1 part: g = dinv * (x @ W1), fp16 out
    __shared__ float Ws[F_IN * HID];
    __shared__ float xs[4][F_IN];
    int tid = threadIdx.x;
    for (int i = tid; i < F_IN * HID; i += 256) Ws[i] = W1[i];
    int lr  = tid >> 6;
    int col = tid & 63;
    int r   = (bid - SCAT_BLKS) * 4 + lr;
    if (col < F_IN) xs[lr][col] = x[(size_t)r * F_IN + col];
    __syncthreads();
    float a = 0.0f;
#pragma unroll
    for (int k = 0; k < F_IN; k++) a = fmaf(xs[lr][k], Ws[k * HID + col], a);
    float dinv = rsqrtf((float)(d_deg[r] + 1));
    d_g[(size_t)r * HID + col] = __float2half(a * dinv);
}

// ---------------- pull aggregation + fused activation (fp16 h out) ----------
__global__ void k_agg(const float* __restrict__ bias, int which) {
    int t = blockIdx.x * blockDim.x + threadIdx.x;
    int node = t >> 3;
    if (node >= N_NODES) return;
    int lane = t & 7;
    int c0 = lane << 3;
    const uint4* gp = (const uint4*)d_g;

    float a[8], b2[8];
    {
        uint4 w = gp[(size_t)node * 8 + lane];      // self loop
        float2 f0 = __half22float2(*(__half2*)&w.x);
        float2 f1 = __half22float2(*(__half2*)&w.y);
        float2 f2 = __half22float2(*(__half2*)&w.z);
        float2 f3 = __half22float2(*(__half2*)&w.w);
        a[0]=f0.x; a[1]=f0.y; a[2]=f1.x; a[3]=f1.y;
        a[4]=f2.x; a[5]=f2.y; a[6]=f3.x; a[7]=f3.y;
    }
#pragma unroll
    for (int k = 0; k < 8; k++) b2[k] = 0.0f;

    int s0 = d_rowstart[node], s1 = d_rowstart[node + 1];
    int i = s0;
    for (; i + 1 < s1; i += 2) {
        int sA = d_csr[i], sB = d_csr[i + 1];
        uint4 uA = gp[(size_t)sA * 8 + lane];
        uint4 uB = gp[(size_t)sB * 8 + lane];
        float2 x0 = __half22float2(*(__half2*)&uA.x), x1 = __half22float2(*(__half2*)&uA.y);
        float2 x2 = __half22float2(*(__half2*)&uA.z), x3 = __half22float2(*(__half2*)&uA.w);
        float2 y0 = __half22float2(*(__half2*)&uB.x), y1 = __half22float2(*(__half2*)&uB.y);
        float2 y2 = __half22float2(*(__half2*)&uB.z), y3 = __half22float2(*(__half2*)&uB.w);
        a[0]+=x0.x; a[1]+=x0.y; a[2]+=x1.x; a[3]+=x1.y;
        a[4]+=x2.x; a[5]+=x2.y; a[6]+=x3.x; a[7]+=x3.y;
        b2[0]+=y0.x; b2[1]+=y0.y; b2[2]+=y1.x; b2[3]+=y1.y;
        b2[4]+=y2.x; b2[5]+=y2.y; b2[6]+=y3.x; b2[7]+=y3.y;
    }
    if (i < s1) {
        int s = d_csr[i];
        uint4 u = gp[(size_t)s * 8 + lane];
        float2 x0 = __half22float2(*(__half2*)&u.x), x1 = __half22float2(*(__half2*)&u.y);
        float2 x2 = __half22float2(*(__half2*)&u.z), x3 = __half22float2(*(__half2*)&u.w);
        a[0]+=x0.x; a[1]+=x0.y; a[2]+=x1.x; a[3]+=x1.y;
        a[4]+=x2.x; a[5]+=x2.y; a[6]+=x3.x; a[7]+=x3.y;
    }
#pragma unroll
    for (int k = 0; k < 8; k++) a[k] += b2[k];

    float di = rsqrtf((float)(d_deg[node] + 1));
    float o[8];
#pragma unroll
    for (int k = 0; k < 8; k++) o[k] = htanh(fmaf(di, a[k], bias[c0 + k]));
    __half2 h0 = __floats2half2_rn(o[0], o[1]);
    __half2 h1 = __floats2half2_rn(o[2], o[3]);
    __half2 h2 = __floats2half2_rn(o[4], o[5]);
    __half2 h3 = __floats2half2_rn(o[6], o[7]);
    uint4 u;
    u.x = *(unsigned*)&h0; u.y = *(unsigned*)&h1;
    u.z = *(unsigned*)&h2; u.w = *(unsigned*)&h3;
    uint4* dst = (uint4*)(which ? d_h2 : d_h1);
    dst[(size_t)node * 8 + lane] = u;
}

// ---------------- layer-2 GEMM via tensor cores: g = dinv*(h1 @ W2) ---------
__global__ void k_gemm2() {
    __shared__ __align__(16) __half As[64 * 64];
    __shared__ __align__(16) __half Bs[64 * 64];
    __shared__ __align__(16) float  Cs[4][16 * 72];
    int tid = threadIdx.x;
    int row0 = blockIdx.x * 64;
    const uint4* wp = (const uint4*)d_W2h;
    uint4* bsp = (uint4*)Bs;
    for (int i = tid; i < 512; i += 128) bsp[i] = wp[i];
    const uint4* hp = (const uint4*)d_h1;
    uint4* asp = (uint4*)As;
    for (int i = tid; i < 512; i += 128) {
        int r = i >> 3, c = i & 7;
        int gr = row0 + r;
        uint4 u = make_uint4(0u, 0u, 0u, 0u);
        if (gr < N_NODES) u = hp[(size_t)gr * 8 + c];
        asp[i] = u;
    }
    __syncthreads();
    int warp = tid >> 5;
    wmma::fragment<wmma::accumulator, 16, 16, 16, float> c[4];
#pragma unroll
    for (int n = 0; n < 4; n++) wmma::fill_fragment(c[n], 0.0f);
#pragma unroll
    for (int k = 0; k < 4; k++) {
        wmma::fragment<wmma::matrix_a, 16, 16, 16, __half, wmma::row_major> af;
        wmma::load_matrix_sync(af, As + warp * 16 * 64 + k * 16, 64);
#pragma unroll
        for (int n = 0; n < 4; n++) {
            wmma::fragment<wmma::matrix_b, 16, 16, 16, __half, wmma::row_major> bf;
            wmma::load_matrix_sync(bf, Bs + k * 16 * 64 + n * 16, 64);
            wmma::mma_sync(c[n], af, bf, c[n]);
        }
    }
#pragma unroll
    for (int n = 0; n < 4; n++)
        wmma::store_matrix_sync(&Cs[warp][n * 16], c[n], 72, wmma::mem_row_major);
    __syncwarp();
    int lane = tid & 31;
    for (int e = lane; e < 16 * 8; e += 32) {
        int r = e >> 3, c8 = e & 7;
        int gr = row0 + warp * 16 + r;
        if (gr >= N_NODES) continue;
        float di = rsqrtf((float)(d_deg[gr] + 1));
        float* crow = &Cs[warp][r * 72 + c8 * 8];
        __half2 h0 = __floats2half2_rn(crow[0] * di, crow[1] * di);
        __half2 h1 = __floats2half2_rn(crow[2] * di, crow[3] * di);
        __half2 h2 = __floats2half2_rn(crow[4] * di, crow[5] * di);
        __half2 h3 = __floats2half2_rn(crow[6] * di, crow[7] * di);
        uint4 u;
        u.x = *(unsigned*)&h0; u.y = *(unsigned*)&h1;
        u.z = *(unsigned*)&h2; u.w = *(unsigned*)&h3;
        ((uint4*)d_g)[(size_t)gr * 8 + c8] = u;
    }
}

// ---------------- pool partials (no atomics) + folded deg reset -------------
#define POOL_BLKS (N_GRAPHS * POOL_CHUNKS)
#define RESET_BLKS ((N_NODES + 139) / 140)
__global__ void k_pool(const float* __restrict__ x) {
    int bid = blockIdx.x;
    if (bid >= POOL_BLKS) {                          // restore deg=0 for next replay
        int i = (bid - POOL_BLKS) * 140 + threadIdx.x;
        if (i < N_NODES) d_deg[i] = 0;
        return;
    }
    int g = bid >> 3;
    int chunk = bid & (POOL_CHUNKS - 1);
    int s = d_starts[g], e = d_starts[g + 1];
    int len = e - s;
    int cs = s + (int)(((long long)len * chunk) / POOL_CHUNKS);
    int ce = s + (int)(((long long)len * (chunk + 1)) / POOL_CHUNKS);
    int c = threadIdx.x;                             // 140 threads
    float sum = 0.0f;
    if (c < F_IN) {
        for (int i = cs; i < ce; i++) sum += x[(size_t)i * F_IN + c];
    } else if (c < F_IN + HID) {
        int cc = c - F_IN;
        for (int i = cs; i < ce; i++) sum += __half2float(d_h1[(size_t)i * HID + cc]);
    } else {
        int cc = c - F_IN - HID;
        for (int i = cs; i < ce; i++) sum += __half2float(d_h2[(size_t)i * HID + cc]);
    }
    d_parts[(g * POOL_CHUNKS + chunk) * FC_DIM + c] = sum;
}

// ---------------- final FC: sum parts, then out = pooled @ fc_W^T + fc_b ----
__global__ void k_fc(const float* __restrict__ fcW, const float* __restrict__ fcb,
                     float* __restrict__ out) {
    __shared__ float ps[FC_DIM];
    int g = blockIdx.x;
    int o = threadIdx.x;                             // 140 threads
    float acc = 0.0f;
#pragma unroll
    for (int ch = 0; ch < POOL_CHUNKS; ch++)
        acc += d_parts[(g * POOL_CHUNKS + ch) * FC_DIM + o];
    ps[o] = acc;
    __syncthreads();
    float a = fcb[o];
#pragma unroll 4
    for (int k = 0; k < FC_DIM; k++) a = fmaf(ps[k], fcW[o * FC_DIM + k], a);
    out[g * FC_DIM + o] = a;
}

// ---------------- launch ----------------------------------------------------
extern "C" void kernel_launch(void* const* d_in, const int* in_sizes, int n_in,
                              void* d_out, int out_size) {
    const float* x    = (const float*)d_in[0];
    const float* W1   = (const float*)d_in[1];
    const float* b1   = (const float*)d_in[2];
    const float* W2   = (const float*)d_in[3];
    const float* b2   = (const float*)d_in[4];
    const float* fcW  = (const float*)d_in[5];
    const float* fcb  = (const float*)d_in[6];
    const void*  ei   = d_in[7];
    const void*  batch= d_in[8];
    float*       out  = (float*)d_out;

    k_probe        <<<16, 256>>>((const int*)ei);
    k_count        <<<SCAT_BLKS + 16, 256>>>(ei, W2);
    k_scan_part    <<<NBLK + 2, 256>>>(batch);
    k_scan_write   <<<NBLK, 256>>>();
    k_scatter_gemm1<<<SCAT_BLKS + GEMM1_BLKS, 256>>>(ei, x, W1);

    k_agg  <<<(N_NODES * 8 + 255) / 256, 256>>>(b1, 0);
    k_gemm2<<<(N_NODES + 63) / 64, 128>>>();
    k_agg  <<<(N_NODES * 8 + 255) / 256, 256>>>(b2, 1);

    k_pool<<<POOL_BLKS + RESET_BLKS, 140>>>(x);
    k_fc  <<<N_GRAPHS, FC_DIM>>>(fcW, fcb, out);
}